// round 3
// baseline (speedup 1.0000x reference)
#include <cuda_runtime.h>

// Problem constants
#define Bz 32
#define Sz 512
#define Hz 1024
#define Lz 2
#define G4 4096                 // 4*Hz
#define BH (Bz*Hz)              // 32768
#define ROWS (Sz*Bz)            // 16384
#define MAIN (Bz*Sz*Hz)         // 16777216
#define NBLK 128

// Static scratch (no runtime allocation allowed)
__device__ float    g_G[(size_t)ROWS * G4];    // x-projection + biases, [row=t*32+b][4H]
__device__ float    g_seq[(size_t)ROWS * Hz];  // layer-0 hidden outputs, [row][H]
__device__ float    g_h[Lz * 2 * BH];          // double-buffered h state per layer
__device__ float    g_c[Lz * BH];              // c state per layer
__device__ unsigned g_flags[Lz * Sz];          // per-step grid-barrier flags

__device__ __forceinline__ float sigf(float x) { return 1.f / (1.f + __expf(-x)); }
__device__ __forceinline__ float tanhfast(float x) {
    float r; asm("tanh.approx.f32 %0, %1;" : "=f"(r) : "f"(x)); return r;
}

// ---------------------------------------------------------------------------
// Big GEMM: g_G[row][n] = dot(X[row][:], W[n][:]) + bi[n] + bh[n]
//   mode 0: X row = x[b][t][:], row = t*32+b   (x is [B,S,H])
//   mode 1: X row = g_seq[row][:]
// 128x128 tile, K-chunk 8, 256 threads, 8x8 quadrant tiles, reg prefetch.
// ---------------------------------------------------------------------------
__global__ __launch_bounds__(256, 2) void gemm128(
    const float* __restrict__ X, const float* __restrict__ W,
    const float* __restrict__ bi, const float* __restrict__ bh, int mode)
{
    __shared__ __align__(16) float Xs[8][132];
    __shared__ __align__(16) float Ws[8][132];

    int tid = threadIdx.x;
    int bn = blockIdx.x, bm = blockIdx.y;
    int lr = tid >> 1;
    int lk = (tid & 1) * 4;

    int row = bm * 128 + lr;
    const float* Xb = mode ? g_seq : X;
    size_t xoff;
    if (mode == 0) { int t = row >> 5, b = row & 31; xoff = (size_t)b * (Sz * Hz) + (size_t)t * Hz; }
    else           { xoff = (size_t)row * Hz; }
    const float* xp = Xb + xoff + lk;
    const float* wp = W + (size_t)(bn * 128 + lr) * Hz + lk;

    float4 xr = *(const float4*)xp;
    float4 wr = *(const float4*)wp;

    float acc[8][8];
#pragma unroll
    for (int i = 0; i < 8; i++)
#pragma unroll
        for (int j = 0; j < 8; j++) acc[i][j] = 0.f;

    int tm4 = (tid >> 4) * 4;
    int tn4 = (tid & 15) * 4;

    for (int k0 = 0; k0 < Hz; k0 += 8) {
        Xs[lk + 0][lr] = xr.x; Xs[lk + 1][lr] = xr.y; Xs[lk + 2][lr] = xr.z; Xs[lk + 3][lr] = xr.w;
        Ws[lk + 0][lr] = wr.x; Ws[lk + 1][lr] = wr.y; Ws[lk + 2][lr] = wr.z; Ws[lk + 3][lr] = wr.w;
        __syncthreads();
        if (k0 + 8 < Hz) {
            xr = *(const float4*)(xp + k0 + 8);
            wr = *(const float4*)(wp + k0 + 8);
        }
#pragma unroll
        for (int kk = 0; kk < 8; kk++) {
            float4 a0 = *(const float4*)&Xs[kk][tm4];
            float4 a1 = *(const float4*)&Xs[kk][64 + tm4];
            float4 b0 = *(const float4*)&Ws[kk][tn4];
            float4 b1 = *(const float4*)&Ws[kk][64 + tn4];
            float av[8] = { a0.x, a0.y, a0.z, a0.w, a1.x, a1.y, a1.z, a1.w };
            float bv[8] = { b0.x, b0.y, b0.z, b0.w, b1.x, b1.y, b1.z, b1.w };
#pragma unroll
            for (int i = 0; i < 8; i++)
#pragma unroll
                for (int j = 0; j < 8; j++) acc[i][j] += av[i] * bv[j];
        }
        __syncthreads();
    }

    int colb = bn * 128;
    float bs[8];
#pragma unroll
    for (int j = 0; j < 8; j++) {
        int c = colb + ((j < 4) ? (tn4 + j) : (64 + tn4 + (j - 4)));
        bs[j] = bi[c] + bh[c];
    }
#pragma unroll
    for (int i = 0; i < 8; i++) {
        int r = bm * 128 + ((i < 4) ? (tm4 + i) : (64 + tm4 + (i - 4)));
        float4 v0 = make_float4(acc[i][0] + bs[0], acc[i][1] + bs[1],
                                acc[i][2] + bs[2], acc[i][3] + bs[3]);
        float4 v1 = make_float4(acc[i][4] + bs[4], acc[i][5] + bs[5],
                                acc[i][6] + bs[6], acc[i][7] + bs[7]);
        *(float4*)&g_G[(size_t)r * G4 + colb + tn4]      = v0;
        *(float4*)&g_G[(size_t)r * G4 + colb + 64 + tn4] = v1;
    }
}

// ---------------------------------------------------------------------------
// Persistent recurrent kernel: one launch covers all 512 steps of one layer.
// 128 blocks x 256 threads, all co-resident (<=148 SMs). Block owns 8 hidden
// units (32 gate-cols) for all 32 batches. Whh panel (32x1024) lives in smem
// for the whole layer. Grid barrier per step via per-step flags + threadfence.
// h-state reads use __ldcg (L2) to dodge stale per-SM L1 lines.
// Dynamic smem: Wsm 32*1024 | hs 32*132 | Ts 32*33  floats.
// ---------------------------------------------------------------------------
#define SM_W   (32 * 1024)
#define SM_H   (32 * 132)
#define SM_T   (32 * 33)
#define SMEMB  ((SM_W + SM_H + SM_T) * 4)

__global__ __launch_bounds__(256, 1) void lstm_persist(
    const float* __restrict__ Whh, float* __restrict__ out, int layer)
{
    extern __shared__ __align__(16) float smraw[];
    float* Wsm = smraw;
    float* hs  = smraw + SM_W;
    float* Ts  = smraw + SM_W + SM_H;

    int tid = threadIdx.x;
    int w = tid >> 5, lane = tid & 31;
    int u0 = blockIdx.x * 8;

    int lb = tid >> 3;            // 0..31 : batch (hs) / gate-col (W load)
    int lk = (tid & 7) * 16;      // 0..112

    // Stage this block's Whh panel into smem once (gc = gate*8 + unit-sub).
    {
        int nl = (lb >> 3) * Hz + u0 + (lb & 7);
        const float* wpg = Whh + (size_t)nl * Hz + (tid & 7) * 128;
        float* dst = Wsm + lb * 1024 + (tid & 7) * 128;
#pragma unroll
        for (int i = 0; i < 128; i += 4)
            *(float4*)(dst + i) = *(const float4*)(wpg + i);
    }
    __syncthreads();

    float* cst = g_c + (size_t)layer * BH;
    unsigned* flags = g_flags + layer * Sz;

    const float* w0p = Wsm + (4 * w + 0) * 1024;
    const float* w1p = Wsm + (4 * w + 1) * 1024;
    const float* w2p = Wsm + (4 * w + 2) * 1024;
    const float* w3p = Wsm + (4 * w + 3) * 1024;
    const float* hsp = hs + lane * 132;

    for (int t = 0; t < Sz; t++) {
        const float* hprev = g_h + (size_t)(layer * 2 + (t & 1)) * BH;
        float* hnext       = g_h + (size_t)(layer * 2 + ((t + 1) & 1)) * BH;

        const float4* hp = (const float4*)(hprev + (size_t)lb * Hz + lk);
        float4 hr0 = __ldcg(hp + 0), hr1 = __ldcg(hp + 1),
               hr2 = __ldcg(hp + 2), hr3 = __ldcg(hp + 3);

        float4 s0 = {0,0,0,0}, s1 = {0,0,0,0}, s2 = {0,0,0,0}, s3 = {0,0,0,0};

        for (int k0 = 0; k0 < Hz; k0 += 128) {
            *(float4*)&hs[lb * 132 + lk]      = hr0;
            *(float4*)&hs[lb * 132 + lk + 4]  = hr1;
            *(float4*)&hs[lb * 132 + lk + 8]  = hr2;
            *(float4*)&hs[lb * 132 + lk + 12] = hr3;
            __syncthreads();
            if (k0 + 128 < Hz) {
                const float4* hp2 = hp + (k0 + 128) / 4;
                hr0 = __ldcg(hp2 + 0); hr1 = __ldcg(hp2 + 1);
                hr2 = __ldcg(hp2 + 2); hr3 = __ldcg(hp2 + 3);
            }
#pragma unroll 8
            for (int kk = 0; kk < 128; kk += 4) {
                float4 hv = *(const float4*)(hsp + kk);
                float4 a  = *(const float4*)(w0p + k0 + kk);
                float4 b  = *(const float4*)(w1p + k0 + kk);
                float4 c  = *(const float4*)(w2p + k0 + kk);
                float4 d  = *(const float4*)(w3p + k0 + kk);
                s0.x += hv.x * a.x; s0.y += hv.y * a.y; s0.z += hv.z * a.z; s0.w += hv.w * a.w;
                s1.x += hv.x * b.x; s1.y += hv.y * b.y; s1.z += hv.z * b.z; s1.w += hv.w * b.w;
                s2.x += hv.x * c.x; s2.y += hv.y * c.y; s2.z += hv.z * c.z; s2.w += hv.w * c.w;
                s3.x += hv.x * d.x; s3.y += hv.y * d.y; s3.z += hv.z * d.z; s3.w += hv.w * d.w;
            }
            __syncthreads();
        }

        Ts[(4 * w + 0) * 33 + lane] = s0.x + s0.y + s0.z + s0.w;
        Ts[(4 * w + 1) * 33 + lane] = s1.x + s1.y + s1.z + s1.w;
        Ts[(4 * w + 2) * 33 + lane] = s2.x + s2.y + s2.z + s2.w;
        Ts[(4 * w + 3) * 33 + lane] = s3.x + s3.y + s3.z + s3.w;
        __syncthreads();

        // cell update: thread -> (batch b = tid>>3, unit-sub us = tid&7)
        {
            int us = tid & 7, b = tid >> 3;
            int u = u0 + us;
            size_t grow = ((size_t)t * 32 + b) * G4;
            float pi = Ts[(us)      * 33 + b] + g_G[grow + u];
            float pf = Ts[(8 + us)  * 33 + b] + g_G[grow + Hz + u];
            float pg = Ts[(16 + us) * 33 + b] + g_G[grow + 2 * Hz + u];
            float po = Ts[(24 + us) * 33 + b] + g_G[grow + 3 * Hz + u];
            float co = cst[b * Hz + u];
            float ii = sigf(pi), ff = sigf(pf), gg = tanhfast(pg), oo = sigf(po);
            float cn = ff * co + ii * gg;
            float hn = oo * tanhfast(cn);
            cst[b * Hz + u] = cn;
            hnext[b * Hz + u] = hn;
            if (layer == 0) g_seq[((size_t)t * 32 + b) * Hz + u] = hn;
            else            out[(size_t)b * (Sz * Hz) + (size_t)t * Hz + u] = hn;
        }

        // grid barrier: writes -> fence -> arrive -> spin -> syncthreads
        __threadfence();
        __syncthreads();
        if (tid == 0) {
            unsigned v = atomicAdd(&flags[t], 1u) + 1u;
            if (v < NBLK) {
                volatile unsigned* f = flags + t;
                while (*f < NBLK) __nanosleep(64);
            }
        }
        __syncthreads();
    }
}

// ---------------------------------------------------------------------------
__global__ void init_state(const float* __restrict__ h0, const float* __restrict__ c0)
{
    int i = blockIdx.x * 256 + threadIdx.x;
    if (i < Lz * BH) {
        int l = i >> 15;          // BH = 32768
        g_h[(l * 2 + 0) * BH + (i & 32767)] = h0[i];
        g_c[i] = c0[i];
    }
    if (i < Lz * Sz) g_flags[i] = 0u;
}

__global__ void write_tail(float* __restrict__ out)
{
    int i = blockIdx.x * 256 + threadIdx.x;
    if (i < Lz * BH) {
        int l = i >> 15;
        int r = i & 32767;
        out[MAIN + i] = g_h[(l * 2 + 0) * BH + r];   // hT (S=512 even -> buffer 0)
        out[MAIN + Lz * BH + i] = g_c[i];            // cT
    }
}

// ---------------------------------------------------------------------------
extern "C" void kernel_launch(void* const* d_in, const int* in_sizes, int n_in,
                              void* d_out, int out_size)
{
    const float* x   = (const float*)d_in[0];
    const float* h0  = (const float*)d_in[1];
    const float* c0  = (const float*)d_in[2];
    const float* Wih = (const float*)d_in[3];
    const float* Whh = (const float*)d_in[4];
    const float* bih = (const float*)d_in[5];
    const float* bhh = (const float*)d_in[6];
    float* out = (float*)d_out;

    cudaFuncSetAttribute(lstm_persist,
                         cudaFuncAttributeMaxDynamicSharedMemorySize, SMEMB);

    init_state<<<256, 256>>>(h0, c0);

    dim3 gg(G4 / 128, ROWS / 128);   // (32, 128)

    // Layer 0: x-projection GEMM, then all 512 steps in one persistent launch
    gemm128<<<gg, 256>>>(x, Wih, bih, bhh, 0);
    lstm_persist<<<NBLK, 256, SMEMB>>>(Whh, out, 0);

    // Layer 1
    gemm128<<<gg, 256>>>(x, Wih + 4 * Hz * Hz, bih + G4, bhh + G4, 1);
    lstm_persist<<<NBLK, 256, SMEMB>>>(Whh + 4 * Hz * Hz, out, 1);

    if (out_size >= MAIN + 2 * Lz * BH)
        write_tail<<<256, 256>>>(out);
}